// round 16
// baseline (speedup 1.0000x reference)
#include <cuda_runtime.h>
#include <cuda_fp16.h>
#include <cstdint>
#include <math.h>

#define IN_DIM  1024
#define INNER   4096
#define HEADS   16
#define HDIM    64
#define BATCH   2
#define SEQ     2048
#define ROWS    (BATCH*SEQ)      // 4096
#define QKV_DIM (HEADS*HDIM*3)   // 3072

// ======================= scratch (static, no allocation) =======================
__device__ float g_proj[ROWS*(size_t)IN_DIM];
__device__ float g_h   [ROWS*(size_t)IN_DIM];
__device__ float g_ff2 [ROWS*(size_t)IN_DIM];

__device__ __half g_Ax   [ROWS*(size_t)IN_DIM];
__device__ __half g_Aattn[ROWS*(size_t)IN_DIM];
__device__ __half g_Ah   [ROWS*(size_t)IN_DIM];
__device__ __half g_Aff1 [ROWS*(size_t)INNER];
__device__ __half g_Wq [IN_DIM*(size_t)QKV_DIM];
__device__ __half g_Wp [IN_DIM*(size_t)IN_DIM];
__device__ __half g_W1 [IN_DIM*(size_t)INNER];
__device__ __half g_W2 [INNER*(size_t)IN_DIM];

__device__ __half g_q1 [BATCH*HEADS*(size_t)SEQ*64];
__device__ __half g_k1 [BATCH*HEADS*(size_t)SEQ*64];
__device__ __half g_v1 [BATCH*HEADS*(size_t)SEQ*64];

// ======================= PTX helpers =======================
__device__ __forceinline__ uint32_t smem_u32(const void* p) {
    uint32_t a;
    asm("{ .reg .u64 t; cvta.to.shared.u64 t, %1; cvt.u32.u64 %0, t; }"
        : "=r"(a) : "l"(p));
    return a;
}

#define CP_ASYNC16(saddr, gptr) \
    asm volatile("cp.async.cg.shared.global [%0], [%1], 16;" :: "r"(saddr), "l"(gptr))
#define CP_COMMIT() asm volatile("cp.async.commit_group;" ::: "memory")
#define CP_WAIT1()  asm volatile("cp.async.wait_group 1;" ::: "memory")
#define CP_WAIT2()  asm volatile("cp.async.wait_group 2;" ::: "memory")

#define LDSM4(r, addr) \
    asm volatile("ldmatrix.sync.aligned.m8n8.x4.shared.b16 {%0,%1,%2,%3}, [%4];" \
        : "=r"((r)[0]), "=r"((r)[1]), "=r"((r)[2]), "=r"((r)[3]) : "r"(addr))

#define LDSM4T(r, addr) \
    asm volatile("ldmatrix.sync.aligned.m8n8.x4.trans.shared.b16 {%0,%1,%2,%3}, [%4];" \
        : "=r"((r)[0]), "=r"((r)[1]), "=r"((r)[2]), "=r"((r)[3]) : "r"(addr))

#define MMA_F16(d, a, b0, b1) \
    asm volatile("mma.sync.aligned.m16n8k16.row.col.f32.f16.f16.f32 " \
        "{%0,%1,%2,%3}, {%4,%5,%6,%7}, {%8,%9}, {%0,%1,%2,%3};" \
        : "+f"((d)[0]), "+f"((d)[1]), "+f"((d)[2]), "+f"((d)[3]) \
        : "r"((a)[0]), "r"((a)[1]), "r"((a)[2]), "r"((a)[3]), "r"(b0), "r"(b1))

__device__ __forceinline__ uint32_t pack_f16(float x, float y) {
    __half2 h = __floats2half2_rn(x, y);
    return *(uint32_t*)&h;
}

// ======================= conversion kernel (5-way fused) =======================
__global__ __launch_bounds__(256)
void convert_all(const float* __restrict__ w0, __half* __restrict__ t0, int n0,
                 const float* __restrict__ w1, __half* __restrict__ t1, int n1,
                 const float* __restrict__ w2, __half* __restrict__ t2, int n2,
                 const float* __restrict__ w3, __half* __restrict__ t3, int n3,
                 const float* __restrict__ w4, __half* __restrict__ t4, int n4)
{
    const float* w; __half* t; int n;
    switch (blockIdx.y) {
        case 0: w = w0; t = t0; n = n0; break;
        case 1: w = w1; t = t1; n = n1; break;
        case 2: w = w2; t = t2; n = n2; break;
        case 3: w = w3; t = t3; n = n3; break;
        default: w = w4; t = t4; n = n4; break;
    }
    int i = blockIdx.x * 256 + threadIdx.x;
    if (i >= n) return;
    float4 v = ((const float4*)w)[i];
    uint2 hv;
    hv.x = pack_f16(v.x, v.y);
    hv.y = pack_f16(v.z, v.w);
    ((uint2*)t)[i] = hv;
}

// ======================= 128x256 GEMM (QKV / FF1): 4 stages, depth-2 wait ======
#define G_A   0
#define G_B   18432
#define G_STG 52224
#define G_SMEM (4*G_STG)            // 208896

template<int MODE>
__global__ __launch_bounds__(256, 1)
void gemm1(const __half* __restrict__ A, const __half* __restrict__ B,
           const float* __restrict__ bias, float* __restrict__ C,
           __half* __restrict__ Aout,
           __half* __restrict__ q1, __half* __restrict__ k1, __half* __restrict__ v1,
           int M, int N, int K)
{
    extern __shared__ char smem[];
    const uint32_t sb = smem_u32(smem);
    const int tid = threadIdx.x;
    const int lane = tid & 31, wid = tid >> 5;
    const int wm = wid & 1, wn = wid >> 1;
    const int m0 = blockIdx.y * 128, n0 = blockIdx.x * 256;
    const int nk = K >> 6;

    auto issue = [&](int kt) {
        const int k0 = kt * 64;
        const uint32_t s = sb + (kt & 3) * G_STG;
        #pragma unroll
        for (int i = 0; i < 12; i++) {
            int c = i * 256 + tid;
            if (c < 1024) {
                int r = c >> 3, cc = c & 7;
                const __half* g = A + (size_t)(m0 + r) * K + k0 + cc * 8;
                CP_ASYNC16(s + G_A + r * 144 + cc * 16, g);
            } else {
                int c2 = c - 1024;
                int r = c2 >> 5, cc = c2 & 31;
                const __half* g = B + (size_t)(k0 + r) * N + n0 + cc * 8;
                CP_ASYNC16(s + G_B + r * 528 + cc * 16, g);
            }
        }
    };

    float acc[4][8][4];
    #pragma unroll
    for (int mt = 0; mt < 4; mt++)
        #pragma unroll
        for (int nt = 0; nt < 8; nt++)
            #pragma unroll
            for (int q = 0; q < 4; q++) acc[mt][nt][q] = 0.f;

    issue(0); CP_COMMIT();
    issue(1); CP_COMMIT();
    issue(2); CP_COMMIT();

    const uint32_t aOff = (uint32_t)(wm * 64 + (lane & 15)) * 144 + (lane >> 4) * 16;
    const uint32_t bRow = (uint32_t)((lane & 7) + ((lane >> 3) & 1) * 8) * 528;
    const uint32_t bCol = (uint32_t)wn * 128 + ((lane >> 4) & 1) * 16;

    for (int kt = 0; kt < nk; kt++) {
        CP_WAIT2();            // group kt complete (kt+1, kt+2 in flight)
        __syncthreads();
        if (kt + 3 < nk) issue(kt + 3);
        CP_COMMIT();

        const uint32_t s = sb + (kt & 3) * G_STG;
        #pragma unroll
        for (int k16 = 0; k16 < 4; k16++) {
            uint32_t ah[4][4];
            #pragma unroll
            for (int mt = 0; mt < 4; mt++)
                LDSM4(ah[mt], s + G_A + aOff + (uint32_t)mt * 16 * 144 + k16 * 32);
            #pragma unroll
            for (int np = 0; np < 4; np++) {
                uint32_t bh[4];
                LDSM4T(bh, s + G_B + bRow + (uint32_t)k16 * 16 * 528 + bCol + np * 32);
                #pragma unroll
                for (int mt = 0; mt < 4; mt++) {
                    MMA_F16(acc[mt][2 * np],     ah[mt], bh[0], bh[1]);
                    MMA_F16(acc[mt][2 * np + 1], ah[mt], bh[2], bh[3]);
                }
            }
        }
    }

    const int crow = m0 + wm * 64 + (lane >> 2);
    const int ccol0 = n0 + wn * 64 + (lane & 3) * 2;

    auto store_qkv = [&](int row, int col, float2 o) {
        int b_ = row >> 11, n_ = row & (SEQ - 1);
        int hh = col / 192, rr = col - hh * 192;
        size_t base = ((size_t)(b_ * HEADS + hh) * SEQ + n_);
        if (rr < 64) {
            *(uint32_t*)(q1 + base * 64 + rr) = pack_f16(o.x * 0.125f, o.y * 0.125f);
        } else if (rr < 128) {
            *(uint32_t*)(k1 + base * 64 + (rr - 64)) = pack_f16(o.x, o.y);
        } else {
            *(uint32_t*)(v1 + base * 64 + (rr - 128)) = pack_f16(o.x, o.y);
        }
    };

    #pragma unroll
    for (int mt = 0; mt < 4; mt++) {
        const int r0 = crow + mt * 16, r1 = r0 + 8;
        #pragma unroll
        for (int nt = 0; nt < 8; nt++) {
            int col = ccol0 + nt * 8;
            float2 bv = *(const float2*)(bias + col);
            float2 o0, o1;
            o0.x = acc[mt][nt][0] + bv.x; o0.y = acc[mt][nt][1] + bv.y;
            o1.x = acc[mt][nt][2] + bv.x; o1.y = acc[mt][nt][3] + bv.y;
            if (MODE == 1) {
                o0.x = fmaxf(o0.x, 0.f); o0.y = fmaxf(o0.y, 0.f);
                o1.x = fmaxf(o1.x, 0.f); o1.y = fmaxf(o1.y, 0.f);
            }
            if (MODE == 0) {
                *(float2*)(C + (size_t)r0 * N + col) = o0;
                *(float2*)(C + (size_t)r1 * N + col) = o1;
            } else if (MODE == 1) {
                *(uint32_t*)(Aout + (size_t)r0 * N + col) = pack_f16(o0.x, o0.y);
                *(uint32_t*)(Aout + (size_t)r1 * N + col) = pack_f16(o1.x, o1.y);
            } else {
                store_qkv(r0, col, o0);
                store_qkv(r1, col, o1);
            }
        }
    }
}

// ======================= 128x128 GEMM (proj / FF2; R15) ========================
#define H_A   0
#define H_B   18432
#define H_STG 35840
#define H_SMEM (3*H_STG)            // 107520

__global__ __launch_bounds__(256, 2)
void gemm128(const __half* __restrict__ A, const __half* __restrict__ B,
             const float* __restrict__ bias, float* __restrict__ C,
             int M, int N, int K)
{
    extern __shared__ char smem[];
    const uint32_t sb = smem_u32(smem);
    const int tid = threadIdx.x;
    const int lane = tid & 31, wid = tid >> 5;
    const int wm = wid & 1, wn = wid >> 1;
    const int m0 = blockIdx.y * 128, n0 = blockIdx.x * 128;
    const int nk = K >> 6;

    auto issue = [&](int kt) {
        const int k0 = kt * 64;
        const uint32_t s = sb + (kt % 3) * H_STG;
        #pragma unroll
        for (int i = 0; i < 8; i++) {
            int c = i * 256 + tid;
            if (c < 1024) {
                int r = c >> 3, cc = c & 7;
                const __half* g = A + (size_t)(m0 + r) * K + k0 + cc * 8;
                CP_ASYNC16(s + H_A + r * 144 + cc * 16, g);
            } else {
                int c2 = c - 1024;
                int r = c2 >> 4, cc = c2 & 15;
                const __half* g = B + (size_t)(k0 + r) * N + n0 + cc * 8;
                CP_ASYNC16(s + H_B + r * 272 + cc * 16, g);
            }
        }
    };

    float acc[4][4][4];
    #pragma unroll
    for (int mt = 0; mt < 4; mt++)
        #pragma unroll
        for (int nt = 0; nt < 4; nt++)
            #pragma unroll
            for (int q = 0; q < 4; q++) acc[mt][nt][q] = 0.f;

    issue(0); CP_COMMIT();
    issue(1); CP_COMMIT();

    const uint32_t aOff = (uint32_t)(wm * 64 + (lane & 15)) * 144 + (lane >> 4) * 16;
    const uint32_t bRow = (uint32_t)((lane & 7) + ((lane >> 3) & 1) * 8) * 272;
    const uint32_t bCol = (uint32_t)wn * 64 + ((lane >> 4) & 1) * 16;

    for (int kt = 0; kt < nk; kt++) {
        CP_WAIT1();
        __syncthreads();
        if (kt + 2 < nk) issue(kt + 2);
        CP_COMMIT();

        const uint32_t s = sb + (kt % 3) * H_STG;
        #pragma unroll
        for (int k16 = 0; k16 < 4; k16++) {
            uint32_t ah[4][4];
            #pragma unroll
            for (int mt = 0; mt < 4; mt++)
                LDSM4(ah[mt], s + H_A + aOff + (uint32_t)mt * 16 * 144 + k16 * 32);
            #pragma unroll
            for (int np = 0; np < 2; np++) {
                uint32_t bh[4];
                LDSM4T(bh, s + H_B + bRow + (uint32_t)k16 * 16 * 272 + bCol + np * 32);
                #pragma unroll
                for (int mt = 0; mt < 4; mt++) {
                    MMA_F16(acc[mt][2 * np],     ah[mt], bh[0], bh[1]);
                    MMA_F16(acc[mt][2 * np + 1], ah[mt], bh[2], bh[3]);
                }
            }
        }
    }

    const int crow = m0 + wm * 64 + (lane >> 2);
    const int ccol0 = n0 + wn * 32 + (lane & 3) * 2;
    #pragma unroll
    for (int mt = 0; mt < 4; mt++) {
        const int r0 = crow + mt * 16, r1 = r0 + 8;
        #pragma unroll
        for (int nt = 0; nt < 4; nt++) {
            int col = ccol0 + nt * 8;
            float2 bv = *(const float2*)(bias + col);
            float2 o0, o1;
            o0.x = acc[mt][nt][0] + bv.x; o0.y = acc[mt][nt][1] + bv.y;
            o1.x = acc[mt][nt][2] + bv.x; o1.y = acc[mt][nt][3] + bv.y;
            *(float2*)(C + (size_t)r0 * N + col) = o0;
            *(float2*)(C + (size_t)r1 * N + col) = o1;
        }
    }
}

// ======================= fp16 flash attention (R14 proven) ====================
#define AT_QS   0
#define AT_KS   36864
#define AT_V    (AT_KS + 2*64*144)
#define AT_SMEM (AT_V + 2*64*144)    // 73728

__global__ __launch_bounds__(256, 1)
void attn_mma(const __half* __restrict__ q1,
              const __half* __restrict__ k1,
              const __half* __restrict__ v1,
              __half* __restrict__ aout)
{
    extern __shared__ char smem[];
    const uint32_t sb = smem_u32(smem);
    const int tid = threadIdx.x, lane = tid & 31, wid = tid >> 5;
    const int bh = blockIdx.y;
    const int q0 = blockIdx.x * 256;
    const char* qg = (const char*)(q1 + ((size_t)bh * SEQ + q0) * 64);
    const char* kg = (const char*)(k1 + (size_t)bh * SEQ * 64);
    const char* vg = (const char*)(v1 + (size_t)bh * SEQ * 64);

    #pragma unroll
    for (int i = 0; i < 8; i++) {
        int c = i * 256 + tid;
        int r = c >> 3, cc = c & 7;
        CP_ASYNC16(sb + AT_QS + r * 144 + cc * 16, qg + (size_t)r * 128 + cc * 16);
    }
    CP_COMMIT();

    auto issue_kv = [&](int kb) {
        const int stg = kb & 1;
        const uint32_t kss = sb + AT_KS + stg * 9216;
        const uint32_t vss = sb + AT_V  + stg * 9216;
        #pragma unroll
        for (int i = 0; i < 2; i++) {
            int c = i * 256 + tid;
            int r = c >> 3, cc = c & 7;
            CP_ASYNC16(kss + r * 144 + cc * 16, kg + (size_t)(kb * 64 + r) * 128 + cc * 16);
            CP_ASYNC16(vss + r * 144 + cc * 16, vg + (size_t)(kb * 64 + r) * 128 + cc * 16);
        }
    };

    issue_kv(0); CP_COMMIT();
    issue_kv(1); CP_COMMIT();

    const int rbase = wid * 32;
    uint32_t aq[4][2][4];
    {
        CP_WAIT2();
        __syncthreads();
        #pragma unroll
        for (int ks = 0; ks < 4; ks++)
            #pragma unroll
            for (int mt = 0; mt < 2; mt++)
                LDSM4(aq[ks][mt], sb + AT_QS + (uint32_t)(rbase + mt * 16 + (lane & 15)) * 144
                          + ks * 32 + (lane >> 4) * 16);
    }

    float oacc[2][8][4];
    #pragma unroll
    for (int mt = 0; mt < 2; mt++)
        #pragma unroll
        for (int nt = 0; nt < 8; nt++)
            #pragma unroll
            for (int q = 0; q < 4; q++) oacc[mt][nt][q] = 0.f;
    float lsum[2][2] = {{0.f, 0.f}, {0.f, 0.f}};

    for (int kb = 0; kb < SEQ / 64; kb++) {
        CP_WAIT1();
        __syncthreads();
        const int stg = kb & 1;
        const uint32_t kss = sb + AT_KS + stg * 9216;

        float sacc[2][8][4];
        #pragma unroll
        for (int mt = 0; mt < 2; mt++)
            #pragma unroll
            for (int nt = 0; nt < 8; nt++)
                #pragma unroll
                for (int q = 0; q < 4; q++) sacc[mt][nt][q] = 0.f;

        #pragma unroll
        for (int ks = 0; ks < 4; ks++) {
            #pragma unroll
            for (int np = 0; np < 4; np++) {
                uint32_t bq[4];
                LDSM4(bq, kss + (uint32_t)(np * 16 + (lane & 7) + ((lane >> 4) & 1) * 8) * 144
                          + ks * 32 + ((lane >> 3) & 1) * 16);
                #pragma unroll
                for (int mt = 0; mt < 2; mt++) {
                    MMA_F16(sacc[mt][2 * np],     aq[ks][mt], bq[0], bq[1]);
                    MMA_F16(sacc[mt][2 * np + 1], aq[ks][mt], bq[2], bq[3]);
                }
            }
        }

        #pragma unroll
        for (int mt = 0; mt < 2; mt++)
            #pragma unroll
            for (int nt = 0; nt < 8; nt++) {
                sacc[mt][nt][0] = __expf(sacc[mt][nt][0]); lsum[mt][0] += sacc[mt][nt][0];
                sacc[mt][nt][1] = __expf(sacc[mt][nt][1]); lsum[mt][0] += sacc[mt][nt][1];
                sacc[mt][nt][2] = __expf(sacc[mt][nt][2]); lsum[mt][1] += sacc[mt][nt][2];
                sacc[mt][nt][3] = __expf(sacc[mt][nt][3]); lsum[mt][1] += sacc[mt][nt][3];
            }

        const uint32_t vss = sb + AT_V + stg * 9216;
        #pragma unroll
        for (int jt = 0; jt < 4; jt++) {
            uint32_t pa[2][4];
            #pragma unroll
            for (int mt = 0; mt < 2; mt++)
                #pragma unroll
                for (int i = 0; i < 4; i++) {
                    const int nt = 2 * jt + (i >> 1);
                    const int c0 = (i & 1) * 2;
                    pa[mt][i] = pack_f16(sacc[mt][nt][c0], sacc[mt][nt][c0 + 1]);
                }
            #pragma unroll
            for (int np = 0; np < 4; np++) {
                uint32_t bv[4];
                LDSM4T(bv, vss + (uint32_t)(jt * 16 + (lane & 7) + ((lane >> 3) & 1) * 8) * 144
                           + np * 32 + ((lane >> 4) & 1) * 16);
                #pragma unroll
                for (int mt = 0; mt < 2; mt++) {
                    MMA_F16(oacc[mt][2 * np],     pa[mt], bv[0], bv[1]);
                    MMA_F16(oacc[mt][2 * np + 1], pa[mt], bv[2], bv[3]);
                }
            }
        }

        __syncthreads();
        if (kb + 2 < SEQ / 64) issue_kv(kb + 2);
        CP_COMMIT();
    }

    const int b = bh >> 4, h = bh & 15;
    #pragma unroll
    for (int mt = 0; mt < 2; mt++) {
        float l0 = lsum[mt][0], l1 = lsum[mt][1];
        l0 += __shfl_xor_sync(0xffffffffu, l0, 1);
        l0 += __shfl_xor_sync(0xffffffffu, l0, 2);
        l1 += __shfl_xor_sync(0xffffffffu, l1, 1);
        l1 += __shfl_xor_sync(0xffffffffu, l1, 2);
        const float inv0 = 1.f / l0, inv1 = 1.f / l1;
        const size_t row1 = (size_t)b * SEQ + q0 + rbase + mt * 16 + (lane >> 2);
        const int col0 = h * 64 + (lane & 3) * 2;
        uint32_t* p0 = (uint32_t*)(aout + row1 * IN_DIM);
        uint32_t* p1 = (uint32_t*)(aout + (row1 + 8) * IN_DIM);
        #pragma unroll
        for (int nt = 0; nt < 8; nt++) {
            const int col = col0 + nt * 8;
            p0[col >> 1] = pack_f16(oacc[mt][nt][0] * inv0, oacc[mt][nt][1] * inv0);
            p1[col >> 1] = pack_f16(oacc[mt][nt][2] * inv1, oacc[mt][nt][3] * inv1);
        }
    }
}

// ======================= LayerNorm =======================
template<bool WH16>
__global__ __launch_bounds__(256)
void ln_kernel(const float* __restrict__ a, const float* __restrict__ b,
               const float* __restrict__ g, const float* __restrict__ beta,
               float* __restrict__ out, __half* __restrict__ aout)
{
    const int row = blockIdx.x;
    const int tid = threadIdx.x;
    const float* pa = a + (size_t)row * IN_DIM;
    const float* pb = b + (size_t)row * IN_DIM;

    float4 va = ((const float4*)pa)[tid];
    float4 vb = ((const float4*)pb)[tid];
    float x0 = va.x + vb.x, x1 = va.y + vb.y, x2 = va.z + vb.z, x3 = va.w + vb.w;

    float s  = x0 + x1 + x2 + x3;
    float s2 = x0 * x0 + x1 * x1 + x2 * x2 + x3 * x3;

    #pragma unroll
    for (int off = 16; off > 0; off >>= 1) {
        s  += __shfl_xor_sync(0xffffffffu, s,  off);
        s2 += __shfl_xor_sync(0xffffffffu, s2, off);
    }
    __shared__ float rs[8], rs2[8], bmean, binv;
    int warp = tid >> 5, lane = tid & 31;
    if (lane == 0) { rs[warp] = s; rs2[warp] = s2; }
    __syncthreads();
    if (warp == 0) {
        float ts  = (lane < 8) ? rs[lane]  : 0.f;
        float ts2 = (lane < 8) ? rs2[lane] : 0.f;
        #pragma unroll
        for (int off = 4; off > 0; off >>= 1) {
            ts  += __shfl_xor_sync(0xffffffffu, ts,  off);
            ts2 += __shfl_xor_sync(0xffffffffu, ts2, off);
        }
        if (lane == 0) {
            float mean = ts * (1.f / IN_DIM);
            float var  = ts2 * (1.f / IN_DIM) - mean * mean;
            bmean = mean;
            binv  = rsqrtf(var + 1e-5f);
        }
    }
    __syncthreads();
    float mean = bmean, inv = binv;

    float4 gv = ((const float4*)g)[tid];
    float4 bt = ((const float4*)beta)[tid];
    float4 o;
    o.x = (x0 - mean) * inv * gv.x + bt.x;
    o.y = (x1 - mean) * inv * gv.y + bt.y;
    o.z = (x2 - mean) * inv * gv.z + bt.z;
    o.w = (x3 - mean) * inv * gv.w + bt.w;
    ((float4*)(out + (size_t)row * IN_DIM))[tid] = o;

    if (WH16) {
        uint2 hv;
        hv.x = pack_f16(o.x, o.y);
        hv.y = pack_f16(o.z, o.w);
        ((uint2*)(aout + (size_t)row * IN_DIM))[tid] = hv;
    }
}

// ======================= host launcher =======================
extern "C" void kernel_launch(void* const* d_in, const int* in_sizes, int n_in,
                              void* d_out, int out_size)
{
    const float* x      = (const float*)d_in[0];
    const float* w_qkv  = (const float*)d_in[1];
    const float* b_qkv  = (const float*)d_in[2];
    const float* w_proj = (const float*)d_in[3];
    const float* b_proj = (const float*)d_in[4];
    const float* g1     = (const float*)d_in[5];
    const float* beta1  = (const float*)d_in[6];
    const float* w_ff1  = (const float*)d_in[7];
    const float* b_ff1  = (const float*)d_in[8];
    const float* w_ff2  = (const float*)d_in[9];
    const float* b_ff2  = (const float*)d_in[10];
    const float* g2     = (const float*)d_in[11];
    const float* beta2  = (const float*)d_in[12];
    float* out = (float*)d_out;

    float *proj, *h, *ff2;
    cudaGetSymbolAddress((void**)&proj, g_proj);
    cudaGetSymbolAddress((void**)&h,    g_h);
    cudaGetSymbolAddress((void**)&ff2,  g_ff2);

    __half *Ax, *Aattn, *Ah, *Aff1, *Wq, *Wp, *W1, *W2, *q1, *k1, *v1;
    cudaGetSymbolAddress((void**)&Ax,    g_Ax);
    cudaGetSymbolAddress((void**)&Aattn, g_Aattn);
    cudaGetSymbolAddress((void**)&Ah,    g_Ah);
    cudaGetSymbolAddress((void**)&Aff1,  g_Aff1);
    cudaGetSymbolAddress((void**)&Wq, g_Wq);
    cudaGetSymbolAddress((void**)&Wp, g_Wp);
    cudaGetSymbolAddress((void**)&W1, g_W1);
    cudaGetSymbolAddress((void**)&W2, g_W2);
    cudaGetSymbolAddress((void**)&q1, g_q1);
    cudaGetSymbolAddress((void**)&k1, g_k1);
    cudaGetSymbolAddress((void**)&v1, g_v1);

    cudaFuncSetAttribute(gemm1<1>, cudaFuncAttributeMaxDynamicSharedMemorySize, G_SMEM);
    cudaFuncSetAttribute(gemm1<2>, cudaFuncAttributeMaxDynamicSharedMemorySize, G_SMEM);
    cudaFuncSetAttribute(gemm128,  cudaFuncAttributeMaxDynamicSharedMemorySize, H_SMEM);
    cudaFuncSetAttribute(attn_mma, cudaFuncAttributeMaxDynamicSharedMemorySize, AT_SMEM);

    dim3 blk(256);

    // fused prep: x activation + all 4 weights fp32->fp16 in ONE launch
    {
        int nx = ROWS * IN_DIM / 4;
        int nq = IN_DIM * QKV_DIM / 4;
        int np = IN_DIM * IN_DIM / 4;
        int n1 = IN_DIM * INNER / 4;
        int n2 = INNER * IN_DIM / 4;
        int maxb = (n1 + 255) / 256;
        convert_all<<<dim3(maxb, 5), blk>>>(x, Ax, nx, w_qkv, Wq, nq,
                                            w_proj, Wp, np, w_ff1, W1, n1,
                                            w_ff2, W2, n2);
    }

    // 1) QKV projection (4-stage pipeline); epilogue scatters q1/k1/v1
    gemm1<2><<<dim3(QKV_DIM/256, ROWS/128), blk, G_SMEM>>>(
        Ax, Wq, b_qkv, nullptr, nullptr, q1, k1, v1, ROWS, QKV_DIM, IN_DIM);

    // 2) attention
    attn_mma<<<dim3(SEQ/256, BATCH*HEADS), blk, AT_SMEM>>>(q1, k1, v1, Aattn);

    // 3) output projection (128x128 tiles)
    gemm128<<<dim3(IN_DIM/128, ROWS/128), blk, H_SMEM>>>(
        Aattn, Wp, b_proj, proj, ROWS, IN_DIM, IN_DIM);

    // 4) LN1(proj + x) -> h (fp32) + Ah (fp16)
    ln_kernel<true><<<ROWS, blk>>>(proj, x, g1, beta1, h, Ah);

    // 5) FF1 + ReLU -> Aff1 (fp16 only; 4-stage pipeline)
    gemm1<1><<<dim3(INNER/256, ROWS/128), blk, G_SMEM>>>(
        Ah, W1, b_ff1, nullptr, Aff1, nullptr, nullptr, nullptr,
        ROWS, INNER, IN_DIM);

    // 6) FF2 (128x128 tiles)
    gemm128<<<dim3(IN_DIM/128, ROWS/128), blk, H_SMEM>>>(
        Aff1, W2, b_ff2, ff2, ROWS, IN_DIM, INNER);

    // 7) LN2(ff2 + h) -> out
    ln_kernel<false><<<ROWS, blk>>>(ff2, h, g2, beta2, out, nullptr);
}

// round 17
// speedup vs baseline: 1.0125x; 1.0125x over previous
#include <cuda_runtime.h>
#include <cuda_fp16.h>
#include <cstdint>
#include <math.h>

#define IN_DIM  1024
#define INNER   4096
#define HEADS   16
#define HDIM    64
#define BATCH   2
#define SEQ     2048
#define ROWS    (BATCH*SEQ)      // 4096
#define QKV_DIM (HEADS*HDIM*3)   // 3072

// ======================= scratch (static, no allocation) =======================
__device__ float g_proj[ROWS*(size_t)IN_DIM];
__device__ float g_h   [ROWS*(size_t)IN_DIM];
__device__ float g_ff2 [ROWS*(size_t)IN_DIM];

__device__ __half g_Ax   [ROWS*(size_t)IN_DIM];
__device__ __half g_Aattn[ROWS*(size_t)IN_DIM];
__device__ __half g_Ah   [ROWS*(size_t)IN_DIM];
__device__ __half g_Aff1 [ROWS*(size_t)INNER];
// single-fp16 weights, TRANSPOSED [N,K]
__device__ __half g_Wq [QKV_DIM*(size_t)IN_DIM];
__device__ __half g_Wp [IN_DIM*(size_t)IN_DIM];
__device__ __half g_W1 [INNER*(size_t)IN_DIM];
__device__ __half g_W2 [IN_DIM*(size_t)INNER];

__device__ __half g_q1 [BATCH*HEADS*(size_t)SEQ*64];
__device__ __half g_k1 [BATCH*HEADS*(size_t)SEQ*64];
__device__ __half g_v1 [BATCH*HEADS*(size_t)SEQ*64];

// ======================= PTX helpers =======================
__device__ __forceinline__ uint32_t smem_u32(const void* p) {
    uint32_t a;
    asm("{ .reg .u64 t; cvta.to.shared.u64 t, %1; cvt.u32.u64 %0, t; }"
        : "=r"(a) : "l"(p));
    return a;
}

#define CP_ASYNC16(saddr, gptr) \
    asm volatile("cp.async.cg.shared.global [%0], [%1], 16;" :: "r"(saddr), "l"(gptr))
#define CP_COMMIT() asm volatile("cp.async.commit_group;" ::: "memory")
#define CP_WAIT1()  asm volatile("cp.async.wait_group 1;" ::: "memory")
#define CP_WAIT2()  asm volatile("cp.async.wait_group 2;" ::: "memory")

#define LDSM4(r, addr) \
    asm volatile("ldmatrix.sync.aligned.m8n8.x4.shared.b16 {%0,%1,%2,%3}, [%4];" \
        : "=r"((r)[0]), "=r"((r)[1]), "=r"((r)[2]), "=r"((r)[3]) : "r"(addr))

#define LDSM4T(r, addr) \
    asm volatile("ldmatrix.sync.aligned.m8n8.x4.trans.shared.b16 {%0,%1,%2,%3}, [%4];" \
        : "=r"((r)[0]), "=r"((r)[1]), "=r"((r)[2]), "=r"((r)[3]) : "r"(addr))

#define MMA_F16(d, a, b0, b1) \
    asm volatile("mma.sync.aligned.m16n8k16.row.col.f32.f16.f16.f32 " \
        "{%0,%1,%2,%3}, {%4,%5,%6,%7}, {%8,%9}, {%0,%1,%2,%3};" \
        : "+f"((d)[0]), "+f"((d)[1]), "+f"((d)[2]), "+f"((d)[3]) \
        : "r"((a)[0]), "r"((a)[1]), "r"((a)[2]), "r"((a)[3]), "r"(b0), "r"(b1))

__device__ __forceinline__ uint32_t pack_f16(float x, float y) {
    __half2 h = __floats2half2_rn(x, y);
    return *(uint32_t*)&h;
}

// ======================= fused prep: x convert + 4 weight transposes ===========
// flat grid: [0,4096) x convert; then Wq 3072, Wp 1024, W1 4096, W2 4096 tiles.
__global__ __launch_bounds__(256)
void prep_all(const float* __restrict__ x,  __half* __restrict__ Ax,
              const float* __restrict__ wq, __half* __restrict__ Wq,
              const float* __restrict__ wp, __half* __restrict__ Wp,
              const float* __restrict__ w1, __half* __restrict__ W1,
              const float* __restrict__ w2, __half* __restrict__ W2)
{
    int b = blockIdx.x;
    if (b < 4096) {
        int i = b * 256 + threadIdx.x;
        float4 v = ((const float4*)x)[i];
        uint2 hv;
        hv.x = pack_f16(v.x, v.y);
        hv.y = pack_f16(v.z, v.w);
        ((uint2*)Ax)[i] = hv;
        return;
    }
    b -= 4096;
    const float* W; __half* T; int K, N;
    if (b < 3072)      {            W = wq; T = Wq; K = 1024; N = 3072; }
    else if (b < 4096) { b -= 3072; W = wp; T = Wp; K = 1024; N = 1024; }
    else if (b < 8192) { b -= 4096; W = w1; T = W1; K = 1024; N = 4096; }
    else               { b -= 8192; W = w2; T = W2; K = 4096; N = 1024; }
    const int tn = N >> 5;
    const int bx = (b % tn) * 32, by = (b / tn) * 32;
    __shared__ float ts[32][33];
    const int tx = threadIdx.x & 31, ty = threadIdx.x >> 5;   // ty 0..7
    #pragma unroll
    for (int i = 0; i < 32; i += 8)
        ts[ty + i][tx] = W[(size_t)(by + ty + i) * N + bx + tx];
    __syncthreads();
    #pragma unroll
    for (int i = 0; i < 32; i += 8)
        T[(size_t)(bx + ty + i) * K + by + tx] = __float2half_rn(ts[tx][ty + i]);
}

// ======================= 128x256 GEMM: B [N,K], non-trans LDSM, BK=64 ==========
// Stage: A 128x144B, B 256x144B. 3 stages.
#define G_A   0
#define G_B   18432
#define G_STG 55296
#define G_SMEM (3*G_STG)            // 165888

template<int MODE>
__global__ __launch_bounds__(256, 1)
void gemm1(const __half* __restrict__ A, const __half* __restrict__ B,
           const float* __restrict__ bias, float* __restrict__ C,
           __half* __restrict__ Aout,
           __half* __restrict__ q1, __half* __restrict__ k1, __half* __restrict__ v1,
           int M, int N, int K)
{
    extern __shared__ char smem[];
    const uint32_t sb = smem_u32(smem);
    const int tid = threadIdx.x;
    const int lane = tid & 31, wid = tid >> 5;
    const int wm = wid & 1, wn = wid >> 1;
    const int m0 = blockIdx.y * 128, n0 = blockIdx.x * 256;
    const int nk = K >> 6;

    auto issue = [&](int kt) {
        const int k0 = kt * 64;
        const uint32_t s = sb + (kt % 3) * G_STG;
        #pragma unroll
        for (int i = 0; i < 12; i++) {
            int c = i * 256 + tid;
            if (c < 1024) {
                int r = c >> 3, cc = c & 7;
                const __half* g = A + (size_t)(m0 + r) * K + k0 + cc * 8;
                CP_ASYNC16(s + G_A + r * 144 + cc * 16, g);
            } else {
                int c2 = c - 1024;          // 0..2047: B rows [N,K]
                int r = c2 >> 3, cc = c2 & 7;
                const __half* g = B + (size_t)(n0 + r) * K + k0 + cc * 8;
                CP_ASYNC16(s + G_B + r * 144 + cc * 16, g);
            }
        }
    };

    float acc[4][8][4];
    #pragma unroll
    for (int mt = 0; mt < 4; mt++)
        #pragma unroll
        for (int nt = 0; nt < 8; nt++)
            #pragma unroll
            for (int q = 0; q < 4; q++) acc[mt][nt][q] = 0.f;

    issue(0); CP_COMMIT();
    issue(1); CP_COMMIT();

    const uint32_t aOff = (uint32_t)(wm * 64 + (lane & 15)) * 144 + (lane >> 4) * 16;
    const uint32_t bOff = (uint32_t)(wn * 64 + ((lane >> 4) << 3) + (lane & 7)) * 144 +
                          ((lane >> 3) & 1) * 16;

    for (int kt = 0; kt < nk; kt++) {
        CP_WAIT1();
        __syncthreads();
        if (kt + 2 < nk) issue(kt + 2);
        CP_COMMIT();

        const uint32_t s = sb + (kt % 3) * G_STG;
        #pragma unroll
        for (int k16 = 0; k16 < 4; k16++) {
            uint32_t ah[4][4];
            #pragma unroll
            for (int mt = 0; mt < 4; mt++)
                LDSM4(ah[mt], s + G_A + aOff + (uint32_t)mt * 16 * 144 + k16 * 32);
            #pragma unroll
            for (int np = 0; np < 4; np++) {
                uint32_t bh[4];
                LDSM4(bh, s + G_B + bOff + (uint32_t)np * 16 * 144 + k16 * 32);
                #pragma unroll
                for (int mt = 0; mt < 4; mt++) {
                    MMA_F16(acc[mt][2 * np],     ah[mt], bh[0], bh[1]);
                    MMA_F16(acc[mt][2 * np + 1], ah[mt], bh[2], bh[3]);
                }
            }
        }
    }

    const int crow = m0 + wm * 64 + (lane >> 2);
    const int ccol0 = n0 + wn * 64 + (lane & 3) * 2;

    auto store_qkv = [&](int row, int col, float2 o) {
        int b_ = row >> 11, n_ = row & (SEQ - 1);
        int hh = col / 192, rr = col - hh * 192;
        size_t base = ((size_t)(b_ * HEADS + hh) * SEQ + n_);
        if (rr < 64) {
            *(uint32_t*)(q1 + base * 64 + rr) = pack_f16(o.x * 0.125f, o.y * 0.125f);
        } else if (rr < 128) {
            *(uint32_t*)(k1 + base * 64 + (rr - 64)) = pack_f16(o.x, o.y);
        } else {
            *(uint32_t*)(v1 + base * 64 + (rr - 128)) = pack_f16(o.x, o.y);
        }
    };

    #pragma unroll
    for (int mt = 0; mt < 4; mt++) {
        const int r0 = crow + mt * 16, r1 = r0 + 8;
        #pragma unroll
        for (int nt = 0; nt < 8; nt++) {
            int col = ccol0 + nt * 8;
            float2 bv = *(const float2*)(bias + col);
            float2 o0, o1;
            o0.x = acc[mt][nt][0] + bv.x; o0.y = acc[mt][nt][1] + bv.y;
            o1.x = acc[mt][nt][2] + bv.x; o1.y = acc[mt][nt][3] + bv.y;
            if (MODE == 1) {
                o0.x = fmaxf(o0.x, 0.f); o0.y = fmaxf(o0.y, 0.f);
                o1.x = fmaxf(o1.x, 0.f); o1.y = fmaxf(o1.y, 0.f);
            }
            if (MODE == 0) {
                *(float2*)(C + (size_t)r0 * N + col) = o0;
                *(float2*)(C + (size_t)r1 * N + col) = o1;
            } else if (MODE == 1) {
                *(uint32_t*)(Aout + (size_t)r0 * N + col) = pack_f16(o0.x, o0.y);
                *(uint32_t*)(Aout + (size_t)r1 * N + col) = pack_f16(o1.x, o1.y);
            } else {
                store_qkv(r0, col, o0);
                store_qkv(r1, col, o1);
            }
        }
    }
}

// ======================= 128x128 GEMM: B [N,K], non-trans LDSM =================
#define H_A   0
#define H_B   18432
#define H_STG 36864
#define H_SMEM (3*H_STG)            // 110592

__global__ __launch_bounds__(256, 2)
void gemm128(const __half* __restrict__ A, const __half* __restrict__ B,
             const float* __restrict__ bias, float* __restrict__ C,
             int M, int N, int K)
{
    extern __shared__ char smem[];
    const uint32_t sb = smem_u32(smem);
    const int tid = threadIdx.x;
    const int lane = tid & 31, wid = tid >> 5;
    const int wm = wid & 1, wn = wid >> 1;
    const int m0 = blockIdx.y * 128, n0 = blockIdx.x * 128;
    const int nk = K >> 6;

    auto issue = [&](int kt) {
        const int k0 = kt * 64;
        const uint32_t s = sb + (kt % 3) * H_STG;
        #pragma unroll
        for (int i = 0; i < 8; i++) {
            int c = i * 256 + tid;
            if (c < 1024) {
                int r = c >> 3, cc = c & 7;
                const __half* g = A + (size_t)(m0 + r) * K + k0 + cc * 8;
                CP_ASYNC16(s + H_A + r * 144 + cc * 16, g);
            } else {
                int c2 = c - 1024;          // B: 128 rows x 8 chunks
                int r = c2 >> 3, cc = c2 & 7;
                const __half* g = B + (size_t)(n0 + r) * K + k0 + cc * 8;
                CP_ASYNC16(s + H_B + r * 144 + cc * 16, g);
            }
        }
    };

    float acc[4][4][4];
    #pragma unroll
    for (int mt = 0; mt < 4; mt++)
        #pragma unroll
        for (int nt = 0; nt < 4; nt++)
            #pragma unroll
            for (int q = 0; q < 4; q++) acc[mt][nt][q] = 0.f;

    issue(0); CP_COMMIT();
    issue(1); CP_COMMIT();

    const uint32_t aOff = (uint32_t)(wm * 64 + (lane & 15)) * 144 + (lane >> 4) * 16;
    const uint32_t bOff = (uint32_t)(wn * 32 + ((lane >> 4) << 3) + (lane & 7)) * 144 +
                          ((lane >> 3) & 1) * 16;

    for (int kt = 0; kt < nk; kt++) {
        CP_WAIT1();
        __syncthreads();
        if (kt + 2 < nk) issue(kt + 2);
        CP_COMMIT();

        const uint32_t s = sb + (kt % 3) * H_STG;
        #pragma unroll
        for (int k16 = 0; k16 < 4; k16++) {
            uint32_t ah[4][4];
            #pragma unroll
            for (int mt = 0; mt < 4; mt++)
                LDSM4(ah[mt], s + H_A + aOff + (uint32_t)mt * 16 * 144 + k16 * 32);
            #pragma unroll
            for (int np = 0; np < 2; np++) {
                uint32_t bh[4];
                LDSM4(bh, s + H_B + bOff + (uint32_t)np * 16 * 144 + k16 * 32);
                #pragma unroll
                for (int mt = 0; mt < 4; mt++) {
                    MMA_F16(acc[mt][2 * np],     ah[mt], bh[0], bh[1]);
                    MMA_F16(acc[mt][2 * np + 1], ah[mt], bh[2], bh[3]);
                }
            }
        }
    }

    const int crow = m0 + wm * 64 + (lane >> 2);
    const int ccol0 = n0 + wn * 32 + (lane & 3) * 2;
    #pragma unroll
    for (int mt = 0; mt < 4; mt++) {
        const int r0 = crow + mt * 16, r1 = r0 + 8;
        #pragma unroll
        for (int nt = 0; nt < 4; nt++) {
            int col = ccol0 + nt * 8;
            float2 bv = *(const float2*)(bias + col);
            float2 o0, o1;
            o0.x = acc[mt][nt][0] + bv.x; o0.y = acc[mt][nt][1] + bv.y;
            o1.x = acc[mt][nt][2] + bv.x; o1.y = acc[mt][nt][3] + bv.y;
            *(float2*)(C + (size_t)r0 * N + col) = o0;
            *(float2*)(C + (size_t)r1 * N + col) = o1;
        }
    }
}

// ======================= fp16 flash attention (R14 proven) ====================
#define AT_QS   0
#define AT_KS   36864
#define AT_V    (AT_KS + 2*64*144)
#define AT_SMEM (AT_V + 2*64*144)    // 73728

__global__ __launch_bounds__(256, 1)
void attn_mma(const __half* __restrict__ q1,
              const __half* __restrict__ k1,
              const __half* __restrict__ v1,
              __half* __restrict__ aout)
{
    extern __shared__ char smem[];
    const uint32_t sb = smem_u32(smem);
    const int tid = threadIdx.x, lane = tid & 31, wid = tid >> 5;
    const int bh = blockIdx.y;
    const int q0 = blockIdx.x * 256;
    const char* qg = (const char*)(q1 + ((size_t)bh * SEQ + q0) * 64);
    const char* kg = (const char*)(k1 + (size_t)bh * SEQ * 64);
    const char* vg = (const char*)(v1 + (size_t)bh * SEQ * 64);

    #pragma unroll
    for (int i = 0; i < 8; i++) {
        int c = i * 256 + tid;
        int r = c >> 3, cc = c & 7;
        CP_ASYNC16(sb + AT_QS + r * 144 + cc * 16, qg + (size_t)r * 128 + cc * 16);
    }
    CP_COMMIT();

    auto issue_kv = [&](int kb) {
        const int stg = kb & 1;
        const uint32_t kss = sb + AT_KS + stg * 9216;
        const uint32_t vss = sb + AT_V  + stg * 9216;
        #pragma unroll
        for (int i = 0; i < 2; i++) {
            int c = i * 256 + tid;
            int r = c >> 3, cc = c & 7;
            CP_ASYNC16(kss + r * 144 + cc * 16, kg + (size_t)(kb * 64 + r) * 128 + cc * 16);
            CP_ASYNC16(vss + r * 144 + cc * 16, vg + (size_t)(kb * 64 + r) * 128 + cc * 16);
        }
    };

    issue_kv(0); CP_COMMIT();
    issue_kv(1); CP_COMMIT();

    const int rbase = wid * 32;
    uint32_t aq[4][2][4];
    {
        CP_WAIT2();
        __syncthreads();
        #pragma unroll
        for (int ks = 0; ks < 4; ks++)
            #pragma unroll
            for (int mt = 0; mt < 2; mt++)
                LDSM4(aq[ks][mt], sb + AT_QS + (uint32_t)(rbase + mt * 16 + (lane & 15)) * 144
                          + ks * 32 + (lane >> 4) * 16);
    }

    float oacc[2][8][4];
    #pragma unroll
    for (int mt = 0; mt < 2; mt++)
        #pragma unroll
        for (int nt = 0; nt < 8; nt++)
            #pragma unroll
            for (int q = 0; q < 4; q++) oacc[mt][nt][q] = 0.f;
    float lsum[2][2] = {{0.f, 0.f}, {0.f, 0.f}};

    for (int kb = 0; kb < SEQ / 64; kb++) {
        CP_WAIT1();
        __syncthreads();
        const int stg = kb & 1;
        const uint32_t kss = sb + AT_KS + stg * 9216;

        float sacc[2][8][4];
        #pragma unroll
        for (int mt = 0; mt < 2; mt++)
            #pragma unroll
            for (int nt = 0; nt < 8; nt++)
                #pragma unroll
                for (int q = 0; q < 4; q++) sacc[mt][nt][q] = 0.f;

        #pragma unroll
        for (int ks = 0; ks < 4; ks++) {
            #pragma unroll
            for (int np = 0; np < 4; np++) {
                uint32_t bq[4];
                LDSM4(bq, kss + (uint32_t)(np * 16 + (lane & 7) + ((lane >> 4) & 1) * 8) * 144
                          + ks * 32 + ((lane >> 3) & 1) * 16);
                #pragma unroll
                for (int mt = 0; mt < 2; mt++) {
                    MMA_F16(sacc[mt][2 * np],     aq[ks][mt], bq[0], bq[1]);
                    MMA_F16(sacc[mt][2 * np + 1], aq[ks][mt], bq[2], bq[3]);
                }
            }
        }

        #pragma unroll
        for (int mt = 0; mt < 2; mt++)
            #pragma unroll
            for (int nt = 0; nt < 8; nt++) {
                sacc[mt][nt][0] = __expf(sacc[mt][nt][0]); lsum[mt][0] += sacc[mt][nt][0];
                sacc[mt][nt][1] = __expf(sacc[mt][nt][1]); lsum[mt][0] += sacc[mt][nt][1];
                sacc[mt][nt][2] = __expf(sacc[mt][nt][2]); lsum[mt][1] += sacc[mt][nt][2];
                sacc[mt][nt][3] = __expf(sacc[mt][nt][3]); lsum[mt][1] += sacc[mt][nt][3];
            }

        const uint32_t vss = sb + AT_V + stg * 9216;
        #pragma unroll
        for (int jt = 0; jt < 4; jt++) {
            uint32_t pa[2][4];
            #pragma unroll
            for (int mt = 0; mt < 2; mt++)
                #pragma unroll
                for (int i = 0; i < 4; i++) {
                    const int nt = 2 * jt + (i >> 1);
                    const int c0 = (i & 1) * 2;
                    pa[mt][i] = pack_f16(sacc[mt][nt][c0], sacc[mt][nt][c0 + 1]);
                }
            #pragma unroll
            for (int np = 0; np < 4; np++) {
                uint32_t bv[4];
                LDSM4T(bv, vss + (uint32_t)(jt * 16 + (lane & 7) + ((lane >> 3) & 1) * 8) * 144
                           + np * 32 + ((lane >> 4) & 1) * 16);
                #pragma unroll
                for (int mt = 0; mt < 2; mt++) {
                    MMA_F16(oacc[mt][2 * np],     pa[mt], bv[0], bv[1]);
                    MMA_F16(oacc[mt][2 * np + 1], pa[mt], bv[2], bv[3]);
                }
            }
        }

        __syncthreads();
        if (kb + 2 < SEQ / 64) issue_kv(kb + 2);
        CP_COMMIT();
    }

    const int b = bh >> 4, h = bh & 15;
    #pragma unroll
    for (int mt = 0; mt < 2; mt++) {
        float l0 = lsum[mt][0], l1 = lsum[mt][1];
        l0 += __shfl_xor_sync(0xffffffffu, l0, 1);
        l0 += __shfl_xor_sync(0xffffffffu, l0, 2);
        l1 += __shfl_xor_sync(0xffffffffu, l1, 1);
        l1 += __shfl_xor_sync(0xffffffffu, l1, 2);
        const float inv0 = 1.f / l0, inv1 = 1.f / l1;
        const size_t row1 = (size_t)b * SEQ + q0 + rbase + mt * 16 + (lane >> 2);
        const int col0 = h * 64 + (lane & 3) * 2;
        uint32_t* p0 = (uint32_t*)(aout + row1 * IN_DIM);
        uint32_t* p1 = (uint32_t*)(aout + (row1 + 8) * IN_DIM);
        #pragma unroll
        for (int nt = 0; nt < 8; nt++) {
            const int col = col0 + nt * 8;
            p0[col >> 1] = pack_f16(oacc[mt][nt][0] * inv0, oacc[mt][nt][1] * inv0);
            p1[col >> 1] = pack_f16(oacc[mt][nt][2] * inv1, oacc[mt][nt][3] * inv1);
        }
    }
}

// ======================= LayerNorm =======================
template<bool WH16>
__global__ __launch_bounds__(256)
void ln_kernel(const float* __restrict__ a, const float* __restrict__ b,
               const float* __restrict__ g, const float* __restrict__ beta,
               float* __restrict__ out, __half* __restrict__ aout)
{
    const int row = blockIdx.x;
    const int tid = threadIdx.x;
    const float* pa = a + (size_t)row * IN_DIM;
    const float* pb = b + (size_t)row * IN_DIM;

    float4 va = ((const float4*)pa)[tid];
    float4 vb = ((const float4*)pb)[tid];
    float x0 = va.x + vb.x, x1 = va.y + vb.y, x2 = va.z + vb.z, x3 = va.w + vb.w;

    float s  = x0 + x1 + x2 + x3;
    float s2 = x0 * x0 + x1 * x1 + x2 * x2 + x3 * x3;

    #pragma unroll
    for (int off = 16; off > 0; off >>= 1) {
        s  += __shfl_xor_sync(0xffffffffu, s,  off);
        s2 += __shfl_xor_sync(0xffffffffu, s2, off);
    }
    __shared__ float rs[8], rs2[8], bmean, binv;
    int warp = tid >> 5, lane = tid & 31;
    if (lane == 0) { rs[warp] = s; rs2[warp] = s2; }
    __syncthreads();
    if (warp == 0) {
        float ts  = (lane < 8) ? rs[lane]  : 0.f;
        float ts2 = (lane < 8) ? rs2[lane] : 0.f;
        #pragma unroll
        for (int off = 4; off > 0; off >>= 1) {
            ts  += __shfl_xor_sync(0xffffffffu, ts,  off);
            ts2 += __shfl_xor_sync(0xffffffffu, ts2, off);
        }
        if (lane == 0) {
            float mean = ts * (1.f / IN_DIM);
            float var  = ts2 * (1.f / IN_DIM) - mean * mean;
            bmean = mean;
            binv  = rsqrtf(var + 1e-5f);
        }
    }
    __syncthreads();
    float mean = bmean, inv = binv;

    float4 gv = ((const float4*)g)[tid];
    float4 bt = ((const float4*)beta)[tid];
    float4 o;
    o.x = (x0 - mean) * inv * gv.x + bt.x;
    o.y = (x1 - mean) * inv * gv.y + bt.y;
    o.z = (x2 - mean) * inv * gv.z + bt.z;
    o.w = (x3 - mean) * inv * gv.w + bt.w;
    ((float4*)(out + (size_t)row * IN_DIM))[tid] = o;

    if (WH16) {
        uint2 hv;
        hv.x = pack_f16(o.x, o.y);
        hv.y = pack_f16(o.z, o.w);
        ((uint2*)(aout + (size_t)row * IN_DIM))[tid] = hv;
    }
}

// ======================= host launcher =======================
extern "C" void kernel_launch(void* const* d_in, const int* in_sizes, int n_in,
                              void* d_out, int out_size)
{
    const float* x      = (const float*)d_in[0];
    const float* w_qkv  = (const float*)d_in[1];
    const float* b_qkv  = (const float*)d_in[2];
    const float* w_proj = (const float*)d_in[3];
    const float* b_proj = (const float*)d_in[4];
    const float* g1     = (const float*)d_in[5];
    const float* beta1  = (const float*)d_in[6];
    const float* w_ff1  = (const float*)d_in[7];
    const float* b_ff1  = (const float*)d_in[8];
    const float* w_ff2  = (const float*)d_in[9];
    const float* b_ff2  = (const float*)d_in[10];
    const float* g2     = (const float*)d_in[11];
    const float* beta2  = (const float*)d_in[12];
    float* out = (float*)d_out;

    float *proj, *h, *ff2;
    cudaGetSymbolAddress((void**)&proj, g_proj);
    cudaGetSymbolAddress((void**)&h,    g_h);
    cudaGetSymbolAddress((void**)&ff2,  g_ff2);

    __half *Ax, *Aattn, *Ah, *Aff1, *Wq, *Wp, *W1, *W2, *q1, *k1, *v1;
    cudaGetSymbolAddress((void**)&Ax,    g_Ax);
    cudaGetSymbolAddress((void**)&Aattn, g_Aattn);
    cudaGetSymbolAddress((void**)&Ah,    g_Ah);
    cudaGetSymbolAddress((void**)&Aff1,  g_Aff1);
    cudaGetSymbolAddress((void**)&Wq, g_Wq);
    cudaGetSymbolAddress((void**)&Wp, g_Wp);
    cudaGetSymbolAddress((void**)&W1, g_W1);
    cudaGetSymbolAddress((void**)&W2, g_W2);
    cudaGetSymbolAddress((void**)&q1, g_q1);
    cudaGetSymbolAddress((void**)&k1, g_k1);
    cudaGetSymbolAddress((void**)&v1, g_v1);

    cudaFuncSetAttribute(gemm1<1>, cudaFuncAttributeMaxDynamicSharedMemorySize, G_SMEM);
    cudaFuncSetAttribute(gemm1<2>, cudaFuncAttributeMaxDynamicSharedMemorySize, G_SMEM);
    cudaFuncSetAttribute(gemm128,  cudaFuncAttributeMaxDynamicSharedMemorySize, H_SMEM);
    cudaFuncSetAttribute(attn_mma, cudaFuncAttributeMaxDynamicSharedMemorySize, AT_SMEM);

    dim3 blk(256);

    // fused prep: x convert + 4 weight transpose+converts, one launch
    prep_all<<<16384, blk>>>(x, Ax, w_qkv, Wq, w_proj, Wp, w_ff1, W1, w_ff2, W2);

    // 1) QKV projection; epilogue scatters q1/k1/v1
    gemm1<2><<<dim3(QKV_DIM/256, ROWS/128), blk, G_SMEM>>>(
        Ax, Wq, b_qkv, nullptr, nullptr, q1, k1, v1, ROWS, QKV_DIM, IN_DIM);

    // 2) attention
    attn_mma<<<dim3(SEQ/256, BATCH*HEADS), blk, AT_SMEM>>>(q1, k1, v1, Aattn);

    // 3) output projection (128x128 tiles)
    gemm128<<<dim3(IN_DIM/128, ROWS/128), blk, H_SMEM>>>(
        Aattn, Wp, b_proj, proj, ROWS, IN_DIM, IN_DIM);

    // 4) LN1(proj + x) -> h (fp32) + Ah (fp16)
    ln_kernel<true><<<ROWS, blk>>>(proj, x, g1, beta1, h, Ah);

    // 5) FF1 + ReLU -> Aff1 (fp16 only)
    gemm1<1><<<dim3(INNER/256, ROWS/128), blk, G_SMEM>>>(
        Ah, W1, b_ff1, nullptr, Aff1, nullptr, nullptr, nullptr,
        ROWS, INNER, IN_DIM);

    // 6) FF2 (128x128 tiles)
    gemm128<<<dim3(IN_DIM/128, ROWS/128), blk, H_SMEM>>>(
        Aff1, W2, b_ff2, ff2, ROWS, IN_DIM, INNER);

    // 7) LN2(ff2 + h) -> out
    ln_kernel<false><<<ROWS, blk>>>(ff2, h, g2, beta2, out, nullptr);
}